// round 1
// baseline (speedup 1.0000x reference)
#include <cuda_runtime.h>

#define BATCH 32
#define CCH   84
#define ANCH  8400
#define KTOP  1000
#define CAP   2048   // max compacted candidates per image (expected ~105)

// Scratch: per-image candidate lists. Key = (f32 bits of conf << 32) | (~anchor_idx)
// -> sorting keys DESCENDING gives conf desc, then anchor idx asc (lax.top_k tie rule).
__device__ int                g_count[BATCH];
__device__ unsigned long long g_keys[BATCH][CAP];

__global__ void zero_counts_kernel() {
    if (threadIdx.x < BATCH) g_count[threadIdx.x] = 0;
}

// One thread per (image, anchor). Reads the 80 class scores (coalesced across
// anchors within a warp), tests valid = (score[cls0] is the max) && conf > 0.1,
// and compacts survivors into g_keys via atomics.
__global__ void score_compact_kernel(const float* __restrict__ preds) {
    const int b = blockIdx.y;
    const int a = blockIdx.x * blockDim.x + threadIdx.x;
    if (a >= ANCH) return;

    const float* p = preds + (size_t)b * CCH * ANCH + a;
    const float s0 = p[4 * ANCH];          // class-0 score
    float rest = -1.0f;
#pragma unroll
    for (int c = 5; c < CCH; ++c)
        rest = fmaxf(rest, p[(size_t)c * ANCH]);

    // argmax == 0  <=>  s0 >= every other class score (first-occurrence rule)
    if (s0 > 0.1f && s0 >= rest) {
        int pos = atomicAdd(&g_count[b], 1);
        if (pos < CAP) {
            g_keys[b][pos] =
                ((unsigned long long)__float_as_uint(s0) << 32)
                | (unsigned)(0xFFFFFFFFu - (unsigned)a);
        }
    }
}

// One block per image: bitonic sort candidates, gather boxes, greedy NMS, emit.
__global__ void __launch_bounds__(256, 1) sort_nms_out_kernel(
    const float* __restrict__ preds, float* __restrict__ out)
{
    const int b   = blockIdx.x;
    const int tid = threadIdx.x;
    const int NT  = 256;

    __shared__ unsigned long long keys[CAP];
    __shared__ float bx1[1024], by1[1024], bx2[1024], by2[1024], barea[1024];
    __shared__ unsigned char keep[1024];

    // Zero this image's output slab (harness poisons d_out).
    float* o = out + (size_t)b * KTOP * 6;
    for (int i = tid; i < KTOP * 6; i += NT) o[i] = 0.0f;

    int cnt = g_count[b];
    if (cnt > CAP) cnt = CAP;
    for (int i = tid; i < CAP; i += NT)
        keys[i] = (i < cnt) ? g_keys[b][i] : 0ull;   // pad keys sort to the end
    __syncthreads();

    // Bitonic sort, descending. Pairs are disjoint per stage; owner = smaller index.
    for (int k = 2; k <= CAP; k <<= 1) {
        for (int j = k >> 1; j > 0; j >>= 1) {
            for (int i = tid; i < CAP; i += NT) {
                int ixj = i ^ j;
                if (ixj > i) {
                    unsigned long long u = keys[i], v = keys[ixj];
                    bool desc = ((i & k) == 0);
                    if ((u < v) == desc) { keys[i] = v; keys[ixj] = u; }
                }
            }
            __syncthreads();
        }
    }

    const int n = (cnt < KTOP) ? cnt : KTOP;
    const float* p = preds + (size_t)b * CCH * ANCH;

    // Gather boxes for the (few) survivors; replicate reference op order exactly.
    for (int r = tid; r < n; r += NT) {
        int idx = (int)(0xFFFFFFFFu - (unsigned)keys[r]);
        float cx = p[idx];
        float cy = p[ANCH + idx];
        float w  = p[2 * ANCH + idx];
        float h  = p[3 * ANCH + idx];
        float hw = __fmul_rn(w, 0.5f), hh = __fmul_rn(h, 0.5f);
        float x1 = __fsub_rn(cx, hw), y1 = __fsub_rn(cy, hh);
        float x2 = __fadd_rn(cx, hw), y2 = __fadd_rn(cy, hh);
        bx1[r] = x1; by1[r] = y1; bx2[r] = x2; by2[r] = y2;
        barea[r] = __fmul_rn(__fsub_rn(x2, x1), __fsub_rn(y2, y1));
        keep[r] = 1;
    }
    __syncthreads();

    // Greedy sequential NMS (matches the fori_loop semantics exactly: at step i,
    // suppress j>i with iou>thr only if keep[i] still true at step i).
    for (int i = 0; i + 1 < n; ++i) {
        if (keep[i]) {
            float xi1 = bx1[i], yi1 = by1[i], xi2 = bx2[i], yi2 = by2[i];
            float ai  = barea[i];
            for (int j = i + 1 + tid; j < n; j += NT) {
                if (!keep[j]) continue;
                float xx1 = fmaxf(xi1, bx1[j]);
                float yy1 = fmaxf(yi1, by1[j]);
                float xx2 = fminf(xi2, bx2[j]);
                float yy2 = fminf(yi2, by2[j]);
                float iw  = fmaxf(__fsub_rn(xx2, xx1), 0.0f);
                float ih  = fmaxf(__fsub_rn(yy2, yy1), 0.0f);
                float inter = __fmul_rn(iw, ih);
                float denom = __fadd_rn(__fsub_rn(__fadd_rn(ai, barea[j]), inter), 1e-7f);
                float iou   = __fdiv_rn(inter, denom);
                if (iou > 0.7f) keep[j] = 0;
            }
        }
        __syncthreads();
    }

    // Emit: [x1,y1,x2,y2]/SCALE, conf, cls(=0). Non-kept rows stay zero.
    const float SCALE_F = 0.3333333333333333f;  // f32 round of python min(640/1080, 640/1920)
    for (int r = tid; r < n; r += NT) {
        if (keep[r]) {
            float conf = __uint_as_float((unsigned)(keys[r] >> 32));
            o[r * 6 + 0] = __fdiv_rn(bx1[r], SCALE_F);
            o[r * 6 + 1] = __fdiv_rn(by1[r], SCALE_F);
            o[r * 6 + 2] = __fdiv_rn(bx2[r], SCALE_F);
            o[r * 6 + 3] = __fdiv_rn(by2[r], SCALE_F);
            o[r * 6 + 4] = conf;
            o[r * 6 + 5] = 0.0f;
        }
    }
}

extern "C" void kernel_launch(void* const* d_in, const int* in_sizes, int n_in,
                              void* d_out, int out_size) {
    const float* preds = (const float*)d_in[0];
    float* out = (float*)d_out;

    zero_counts_kernel<<<1, 32>>>();

    dim3 grid((ANCH + 255) / 256, BATCH);
    score_compact_kernel<<<grid, 256>>>(preds);

    sort_nms_out_kernel<<<BATCH, 256>>>(preds, out);
}